// round 15
// baseline (speedup 1.0000x reference)
#include <cuda_runtime.h>
#include <cuda_fp16.h>
#include <cstdint>

#define T_LEN 16384
#define HID 1024
#define HID3 3072
#define L_CHUNK 128
#define NCHUNK 128

#define BN 128
#define BK 32           // K per stage, in halves (64 bytes)
#define ASTRH 40        // row stride in halves (80 B): conflict-free LDSM phases
#define SMEM_BYTES_MT(MT) (2 * ((MT) * 32 + BN) * ASTRH * 2)

// ---------------- scratch ----------------------------------------------------
__device__ __half g_hidden[T_LEN * HID3];   // [h_re | h_im | inputs] per row
__device__ __half g_bcat[2048 * HID];       // [n][k]: n<1024 re, else im (K-major)
__device__ __half g_w2[HID * HID3];         // [o][k]: [C_re | -C_im | D^T]
__device__ float g_lam_re[HID], g_lam_im[HID];
__device__ float g_lamL_re[HID], g_lamL_im[HID];
__device__ float g_end_re[NCHUNK * HID], g_end_im[NCHUNK * HID];
__device__ float g_carry_re[NCHUNK * HID], g_carry_im[NCHUNK * HID];

// ---------------- helpers ----------------------------------------------------
__device__ __forceinline__ void cp16(void* dst, const void* src) {
    uint32_t d = (uint32_t)__cvta_generic_to_shared(dst);
    asm volatile("cp.async.cg.shared.global [%0], [%1], 16;" :: "r"(d), "l"(src));
}
__device__ __forceinline__ void ldsm4(uint32_t* r, uint32_t addr) {
    asm volatile("ldmatrix.sync.aligned.m8n8.x4.shared.b16 {%0,%1,%2,%3}, [%4];"
                 : "=r"(r[0]), "=r"(r[1]), "=r"(r[2]), "=r"(r[3]) : "r"(addr));
}
__device__ __forceinline__ void mma_f16(float* c, const uint32_t* a, const uint32_t* b) {
    asm volatile(
        "mma.sync.aligned.m16n8k16.row.col.f32.f16.f16.f32 "
        "{%0,%1,%2,%3},{%4,%5,%6,%7},{%8,%9},{%0,%1,%2,%3};"
        : "+f"(c[0]), "+f"(c[1]), "+f"(c[2]), "+f"(c[3])
        : "r"(a[0]), "r"(a[1]), "r"(a[2]), "r"(a[3]), "r"(b[0]), "r"(b[1]));
}
__device__ __forceinline__ void store2(float* p, float x, float y) {
    *(float2*)p = make_float2(x, y);
}
__device__ __forceinline__ void store2(__half* p, float x, float y) {
    *(__half2*)p = __floats2half2_rn(x, y);
}

// ---------------- prep -------------------------------------------------------
__global__ void prep_lambda(const float* __restrict__ nu_log,
                            const float* __restrict__ theta_log) {
    int h = threadIdx.x;
    float a = -expf(nu_log[h]);
    float b = expf(theta_log[h]);
    float m = expf(a);
    g_lam_re[h] = m * cosf(b);
    g_lam_im[h] = m * sinf(b);
    double aL = (double)a * (double)L_CHUNK;
    double bL = (double)b * (double)L_CHUNK;
    double mL = exp(aL);
    g_lamL_re[h] = (float)(mL * cos(bL));
    g_lamL_im[h] = (float)(mL * sin(bL));
}

// bcat[n][k] = B[k][n] * exp(gamma[k])  (tile transpose, fused re/im)
__global__ void prep_bcat(const float* __restrict__ B_re,
                          const float* __restrict__ B_im,
                          const float* __restrict__ gamma_log) {
    __shared__ float tr[32][33], ti[32][33];
    int kb = blockIdx.y * 32, nb = blockIdx.x * 32;
    int tx = threadIdx.x;
    for (int r = threadIdx.y; r < 32; r += 8) {
        int k = kb + r;
        float g = expf(gamma_log[k]);
        tr[r][tx] = B_re[(size_t)k * HID + nb + tx] * g;
        ti[r][tx] = B_im[(size_t)k * HID + nb + tx] * g;
    }
    __syncthreads();
    for (int r = threadIdx.y; r < 32; r += 8) {
        int n = nb + r;
        g_bcat[(size_t)n * HID + kb + tx]          = __float2half_rn(tr[tx][r]);
        g_bcat[(size_t)(n + 1024) * HID + kb + tx] = __float2half_rn(ti[tx][r]);
    }
}

// w2[o][k], k<1024: C_re[o][k]; k<2048: -C_im[o][k-1024]  (coalesced copy)
__global__ void prep_w2_c(const float* __restrict__ C_re,
                          const float* __restrict__ C_im) {
    int idx = blockIdx.x * blockDim.x + threadIdx.x;   // 0 .. 1024*2048-1
    int o = idx >> 11, k = idx & 2047;
    float v = (k < 1024) ? C_re[(size_t)o * HID + k]
                         : -C_im[(size_t)o * HID + (k - 1024)];
    g_w2[(size_t)o * HID3 + k] = __float2half_rn(v);
}

// w2[o][2048+j] = D[j][o]  (tile transpose)
__global__ void prep_w2_d(const float* __restrict__ D) {
    __shared__ float td[32][33];
    int jb = blockIdx.y * 32, ob = blockIdx.x * 32;
    int tx = threadIdx.x;
    for (int r = threadIdx.y; r < 32; r += 8)
        td[r][tx] = D[(size_t)(jb + r) * HID + ob + tx];
    __syncthreads();
    for (int r = threadIdx.y; r < 32; r += 8)
        g_w2[(size_t)(ob + r) * HID3 + 2048 + jb + tx] = __float2half_rn(td[tx][r]);
}

__global__ void copy_inputs(const float* __restrict__ inputs) {
    int idx = blockIdx.x * blockDim.x + threadIdx.x;   // 8 floats per thread
    int row = idx >> 7, c8 = idx & 127;
    const float4* in4 = (const float4*)inputs;
    float4 v0 = in4[(size_t)row * 256 + c8 * 2];
    float4 v1 = in4[(size_t)row * 256 + c8 * 2 + 1];
    __half2 h0 = __floats2half2_rn(v0.x, v0.y);
    __half2 h1 = __floats2half2_rn(v0.z, v0.w);
    __half2 h2 = __floats2half2_rn(v1.x, v1.y);
    __half2 h3 = __floats2half2_rn(v1.z, v1.w);
    uint4 u = make_uint4(*(uint32_t*)&h0, *(uint32_t*)&h1,
                         *(uint32_t*)&h2, *(uint32_t*)&h3);
    *(uint4*)&g_hidden[(size_t)row * HID3 + 2048 + c8 * 8] = u;
}

// ---------------- FP16 tensor-core GEMM (f32 acc, ldmatrix) ------------------
// C[M,N] = A[M,K] @ Bt[N,K]^T. A row-major halves (lda), Bt K-major rows (ldb).
// MT = m16-tiles per warp in M; block M-tile = MT*32 rows.
template <typename OutT, int MT>
__global__ __launch_bounds__(256, 2)
void h16gemm(const __half* __restrict__ A, const __half* __restrict__ Bt,
             OutT* __restrict__ C, int K, int lda, int ldb, int ldc) {
    constexpr int BMt = MT * 32;
    extern __shared__ __half smem[];
    __half (*As)[ASTRH] = (__half (*)[ASTRH])smem;                       // [2*BMt]
    __half (*Bs)[ASTRH] = (__half (*)[ASTRH])(smem + 2 * BMt * ASTRH);   // [2*BN]

    const int tid = threadIdx.x;
    const int bm = blockIdx.y * BMt;
    const int bn = blockIdx.x * BN;

    const int lane = tid & 31, wid = tid >> 5;
    const int wm = (wid >> 2) * (MT * 16);
    const int wn = (wid & 3) * 32;
    const int g = lane >> 2, t = lane & 3;

    // ldmatrix lane map: lanes 0-15 -> rows 0-15 (k+0), lanes 16-31 -> rows (k+8)
    const int lrow = lane & 15;
    const int khalf = (lane >> 4) * 8;
    const uint32_t aBase = (uint32_t)__cvta_generic_to_shared(&As[wm + lrow][khalf]);
    const uint32_t bBase = (uint32_t)__cvta_generic_to_shared(&Bs[wn + lrow][khalf]);

    float acc[MT][4][4];
#pragma unroll
    for (int mt = 0; mt < MT; mt++)
#pragma unroll
        for (int nt = 0; nt < 4; nt++)
#pragma unroll
            for (int i = 0; i < 4; i++) acc[mt][nt][i] = 0.f;

    const int niter = K / BK;

    // A tile: BMt*4 cp16 ops; B tile: 512 ops; 256 threads
#define LOAD_STAGE(buf, it)                                                   \
    {                                                                         \
        _Pragma("unroll")                                                     \
        for (int tt = 0; tt < BMt / 64; tt++) {                               \
            int j = tid + tt * 256;                                           \
            int row = j >> 2, c8 = j & 3;                                     \
            cp16(&As[(buf) * BMt + row][c8 * 8],                              \
                 A + (size_t)(bm + row) * lda + (it) * BK + c8 * 8);          \
        }                                                                     \
        _Pragma("unroll")                                                     \
        for (int tt = 0; tt < 2; tt++) {                                      \
            int j = tid + tt * 256;                                           \
            int row = j >> 2, c8 = j & 3;                                     \
            cp16(&Bs[(buf) * BN + row][c8 * 8],                               \
                 Bt + (size_t)(bn + row) * ldb + (it) * BK + c8 * 8);         \
        }                                                                     \
        asm volatile("cp.async.commit_group;");                               \
    }

    LOAD_STAGE(0, 0)

    for (int i = 0; i < niter; i++) {
        if (i + 1 < niter) {
            LOAD_STAGE((i + 1) & 1, i + 1)
            asm volatile("cp.async.wait_group 1;");
        } else {
            asm volatile("cp.async.wait_group 0;");
        }
        __syncthreads();

        const uint32_t aOff = aBase + (i & 1) * (BMt * ASTRH * 2);
        const uint32_t bOff = bBase + (i & 1) * (BN * ASTRH * 2);
#pragma unroll
        for (int ks = 0; ks < 2; ks++) {
            const uint32_t kOff = ks * 32;   // 16 halves = 32 bytes
            uint32_t af[MT][4], bf[4][2];
#pragma unroll
            for (int mt = 0; mt < MT; mt++)
                ldsm4(af[mt], aOff + mt * (16 * ASTRH * 2) + kOff);
#pragma unroll
            for (int np = 0; np < 2; np++) {
                uint32_t r[4];
                ldsm4(r, bOff + np * (16 * ASTRH * 2) + kOff);
                bf[np * 2 + 0][0] = r[0];
                bf[np * 2 + 1][0] = r[1];
                bf[np * 2 + 0][1] = r[2];
                bf[np * 2 + 1][1] = r[3];
            }
#pragma unroll
            for (int mt = 0; mt < MT; mt++)
#pragma unroll
                for (int nt = 0; nt < 4; nt++)
                    mma_f16(acc[mt][nt], af[mt], bf[nt]);
        }
        __syncthreads();
    }
#undef LOAD_STAGE

    OutT* Cb = C + (size_t)(bm + wm) * ldc + bn + wn;
#pragma unroll
    for (int mt = 0; mt < MT; mt++) {
#pragma unroll
        for (int nt = 0; nt < 4; nt++) {
            const int r0 = mt * 16 + g;
            const int c0 = nt * 8 + t * 2;
            store2(&Cb[(size_t)r0 * ldc + c0], acc[mt][nt][0], acc[mt][nt][1]);
            store2(&Cb[(size_t)(r0 + 8) * ldc + c0], acc[mt][nt][2], acc[mt][nt][3]);
        }
    }
}

// ---------------- chunked complex scan (2 channels/thread, half2 loads) ------
__global__ void scan_ends() {
    int gidx = blockIdx.x * blockDim.x + threadIdx.x;  // 0 .. NCHUNK*512-1
    int p = gidx & 511, chunk = gidx >> 9;
    int h0 = 2 * p;
    float lr0 = g_lam_re[h0],     li0 = g_lam_im[h0];
    float lr1 = g_lam_re[h0 + 1], li1 = g_lam_im[h0 + 1];
    float sr0 = 0.f, si0 = 0.f, sr1 = 0.f, si1 = 0.f;
    size_t base = (size_t)chunk * L_CHUNK * HID3 + h0;
#pragma unroll 4
    for (int tt = 0; tt < L_CHUNK; tt++) {
        float2 r = __half22float2(*(const __half2*)&g_hidden[base]);
        float2 m = __half22float2(*(const __half2*)&g_hidden[base + 1024]);
        base += HID3;
        float nr0 = fmaf(lr0, sr0, fmaf(-li0, si0, r.x));
        float ni0 = fmaf(lr0, si0, fmaf(li0, sr0, m.x));
        float nr1 = fmaf(lr1, sr1, fmaf(-li1, si1, r.y));
        float ni1 = fmaf(lr1, si1, fmaf(li1, sr1, m.y));
        sr0 = nr0; si0 = ni0; sr1 = nr1; si1 = ni1;
    }
    g_end_re[chunk * HID + h0]     = sr0;
    g_end_im[chunk * HID + h0]     = si0;
    g_end_re[chunk * HID + h0 + 1] = sr1;
    g_end_im[chunk * HID + h0 + 1] = si1;
}

__global__ void scan_carries() {
    int h = blockIdx.x * blockDim.x + threadIdx.x;
    float lr = g_lamL_re[h], li = g_lamL_im[h];
    float cr = 0.f, ci = 0.f;
    for (int c = 0; c < NCHUNK; c++) {
        g_carry_re[c * HID + h] = cr;
        g_carry_im[c * HID + h] = ci;
        float er = g_end_re[c * HID + h], ei = g_end_im[c * HID + h];
        float nr = fmaf(lr, cr, fmaf(-li, ci, er));
        float ni = fmaf(lr, ci, fmaf(li, cr, ei));
        cr = nr; ci = ni;
    }
}

__global__ void scan_apply() {
    int gidx = blockIdx.x * blockDim.x + threadIdx.x;  // 0 .. NCHUNK*512-1
    int p = gidx & 511, chunk = gidx >> 9;
    int h0 = 2 * p;
    float lr0 = g_lam_re[h0],     li0 = g_lam_im[h0];
    float lr1 = g_lam_re[h0 + 1], li1 = g_lam_im[h0 + 1];
    float sr0 = g_carry_re[chunk * HID + h0];
    float si0 = g_carry_im[chunk * HID + h0];
    float sr1 = g_carry_re[chunk * HID + h0 + 1];
    float si1 = g_carry_im[chunk * HID + h0 + 1];
    size_t base = (size_t)chunk * L_CHUNK * HID3 + h0;
#pragma unroll 4
    for (int tt = 0; tt < L_CHUNK; tt++) {
        float2 r = __half22float2(*(const __half2*)&g_hidden[base]);
        float2 m = __half22float2(*(const __half2*)&g_hidden[base + 1024]);
        float nr0 = fmaf(lr0, sr0, fmaf(-li0, si0, r.x));
        float ni0 = fmaf(lr0, si0, fmaf(li0, sr0, m.x));
        float nr1 = fmaf(lr1, sr1, fmaf(-li1, si1, r.y));
        float ni1 = fmaf(lr1, si1, fmaf(li1, sr1, m.y));
        sr0 = nr0; si0 = ni0; sr1 = nr1; si1 = ni1;
        *(__half2*)&g_hidden[base]        = __floats2half2_rn(sr0, sr1);
        *(__half2*)&g_hidden[base + 1024] = __floats2half2_rn(si0, si1);
        base += HID3;
    }
}

// ---------------- launch -----------------------------------------------------
extern "C" void kernel_launch(void* const* d_in, const int* in_sizes, int n_in,
                              void* d_out, int out_size) {
    const float* inputs    = (const float*)d_in[0];
    const float* nu_log    = (const float*)d_in[1];
    const float* theta_log = (const float*)d_in[2];
    const float* gamma_log = (const float*)d_in[3];
    const float* B_re      = (const float*)d_in[4];
    const float* B_im      = (const float*)d_in[5];
    const float* C_re      = (const float*)d_in[6];
    const float* C_im      = (const float*)d_in[7];
    const float* Dmat      = (const float*)d_in[8];
    float* out = (float*)d_out;

    __half *hidden, *bcat, *w2;
    cudaGetSymbolAddress((void**)&hidden, g_hidden);
    cudaGetSymbolAddress((void**)&bcat, g_bcat);
    cudaGetSymbolAddress((void**)&w2, g_w2);

    cudaFuncSetAttribute((const void*)h16gemm<__half, 4>,
                         cudaFuncAttributeMaxDynamicSharedMemorySize,
                         SMEM_BYTES_MT(4));
    cudaFuncSetAttribute((const void*)h16gemm<float, 2>,
                         cudaFuncAttributeMaxDynamicSharedMemorySize,
                         SMEM_BYTES_MT(2));

    prep_lambda<<<1, HID>>>(nu_log, theta_log);
    prep_bcat<<<dim3(32, 32), dim3(32, 8)>>>(B_re, B_im, gamma_log);
    prep_w2_c<<<(HID * 2048) / 256, 256>>>(C_re, C_im);
    prep_w2_d<<<dim3(32, 32), dim3(32, 8)>>>(Dmat);
    copy_inputs<<<(T_LEN * HID / 8) / 256, 256>>>(inputs);

    // GEMM1: hidden[:, :2048] = u16 @ bcat^T  (128x128 tiles, 2048 CTAs)
    h16gemm<__half, 4><<<dim3(2048 / BN, T_LEN / 128), 256, SMEM_BYTES_MT(4)>>>(
        hidden + 2048, bcat, hidden, HID, HID3, HID, HID3);

    // complex diagonal scan, in-place (2 channels per thread)
    scan_ends<<<(NCHUNK * 512) / 256, 256>>>();
    scan_carries<<<HID / 256, 256>>>();
    scan_apply<<<(NCHUNK * 512) / 256, 256>>>();

    // GEMM2: out = [h_re|h_im|inputs] @ w2^T  (64x128 tiles, 2048 CTAs ->
    // 6.92 waves instead of 3.46: kills the 56us partial-wave tensor idle)
    h16gemm<float, 2><<<dim3(HID / BN, T_LEN / 64), 256, SMEM_BYTES_MT(2)>>>(
        hidden, w2, out, HID3, HID3, HID3, HID);
}

// round 16
// speedup vs baseline: 1.7450x; 1.7450x over previous
#include <cuda_runtime.h>
#include <cuda_fp16.h>
#include <cstdint>

#define T_LEN 16384
#define HID 1024
#define HID3 3072
#define L_CHUNK 128
#define NCHUNK 128

#define BM 128
#define BN 128
#define BK 64           // K per stage, in halves (128 bytes)
#define ASTRH 72        // row stride in halves (144 B): 36 words -> LDSM phases 4r mod 32, conflict-free
#define SMEM_BYTES (2 * (BM * ASTRH + BN * ASTRH) * 2)   // 2 stages, A+B: 73728 B

// ---------------- scratch ----------------------------------------------------
__device__ __half g_hidden[T_LEN * HID3];   // [h_re | h_im | inputs] per row
__device__ __half g_bcat[2048 * HID];       // [n][k]: n<1024 re, else im (K-major)
__device__ __half g_w2[HID * HID3];         // [o][k]: [C_re | -C_im | D^T]
__device__ float g_lam_re[HID], g_lam_im[HID];
__device__ float g_lamL_re[HID], g_lamL_im[HID];
__device__ float g_end_re[NCHUNK * HID], g_end_im[NCHUNK * HID];
__device__ float g_carry_re[NCHUNK * HID], g_carry_im[NCHUNK * HID];

// ---------------- helpers ----------------------------------------------------
__device__ __forceinline__ void cp16(void* dst, const void* src) {
    uint32_t d = (uint32_t)__cvta_generic_to_shared(dst);
    asm volatile("cp.async.cg.shared.global [%0], [%1], 16;" :: "r"(d), "l"(src));
}
__device__ __forceinline__ void ldsm4(uint32_t* r, uint32_t addr) {
    asm volatile("ldmatrix.sync.aligned.m8n8.x4.shared.b16 {%0,%1,%2,%3}, [%4];"
                 : "=r"(r[0]), "=r"(r[1]), "=r"(r[2]), "=r"(r[3]) : "r"(addr));
}
__device__ __forceinline__ void mma_f16(float* c, const uint32_t* a, const uint32_t* b) {
    asm volatile(
        "mma.sync.aligned.m16n8k16.row.col.f32.f16.f16.f32 "
        "{%0,%1,%2,%3},{%4,%5,%6,%7},{%8,%9},{%0,%1,%2,%3};"
        : "+f"(c[0]), "+f"(c[1]), "+f"(c[2]), "+f"(c[3])
        : "r"(a[0]), "r"(a[1]), "r"(a[2]), "r"(a[3]), "r"(b[0]), "r"(b[1]));
}
__device__ __forceinline__ void store2(float* p, float x, float y) {
    *(float2*)p = make_float2(x, y);
}
__device__ __forceinline__ void store2(__half* p, float x, float y) {
    *(__half2*)p = __floats2half2_rn(x, y);
}

// ---------------- prep -------------------------------------------------------
__global__ void prep_lambda(const float* __restrict__ nu_log,
                            const float* __restrict__ theta_log) {
    int h = threadIdx.x;
    float a = -expf(nu_log[h]);
    float b = expf(theta_log[h]);
    float m = expf(a);
    g_lam_re[h] = m * cosf(b);
    g_lam_im[h] = m * sinf(b);
    double aL = (double)a * (double)L_CHUNK;
    double bL = (double)b * (double)L_CHUNK;
    double mL = exp(aL);
    g_lamL_re[h] = (float)(mL * cos(bL));
    g_lamL_im[h] = (float)(mL * sin(bL));
}

// bcat[n][k] = B[k][n] * exp(gamma[k])  (tile transpose, fused re/im)
__global__ void prep_bcat(const float* __restrict__ B_re,
                          const float* __restrict__ B_im,
                          const float* __restrict__ gamma_log) {
    __shared__ float tr[32][33], ti[32][33];
    int kb = blockIdx.y * 32, nb = blockIdx.x * 32;
    int tx = threadIdx.x;
    for (int r = threadIdx.y; r < 32; r += 8) {
        int k = kb + r;
        float g = expf(gamma_log[k]);
        tr[r][tx] = B_re[(size_t)k * HID + nb + tx] * g;
        ti[r][tx] = B_im[(size_t)k * HID + nb + tx] * g;
    }
    __syncthreads();
    for (int r = threadIdx.y; r < 32; r += 8) {
        int n = nb + r;
        g_bcat[(size_t)n * HID + kb + tx]          = __float2half_rn(tr[tx][r]);
        g_bcat[(size_t)(n + 1024) * HID + kb + tx] = __float2half_rn(ti[tx][r]);
    }
}

// w2[o][k], k<1024: C_re[o][k]; k<2048: -C_im[o][k-1024]  (coalesced copy)
__global__ void prep_w2_c(const float* __restrict__ C_re,
                          const float* __restrict__ C_im) {
    int idx = blockIdx.x * blockDim.x + threadIdx.x;   // 0 .. 1024*2048-1
    int o = idx >> 11, k = idx & 2047;
    float v = (k < 1024) ? C_re[(size_t)o * HID + k]
                         : -C_im[(size_t)o * HID + (k - 1024)];
    g_w2[(size_t)o * HID3 + k] = __float2half_rn(v);
}

// w2[o][2048+j] = D[j][o]  (tile transpose)
__global__ void prep_w2_d(const float* __restrict__ D) {
    __shared__ float td[32][33];
    int jb = blockIdx.y * 32, ob = blockIdx.x * 32;
    int tx = threadIdx.x;
    for (int r = threadIdx.y; r < 32; r += 8)
        td[r][tx] = D[(size_t)(jb + r) * HID + ob + tx];
    __syncthreads();
    for (int r = threadIdx.y; r < 32; r += 8)
        g_w2[(size_t)(ob + r) * HID3 + 2048 + jb + tx] = __float2half_rn(td[tx][r]);
}

__global__ void copy_inputs(const float* __restrict__ inputs) {
    int idx = blockIdx.x * blockDim.x + threadIdx.x;   // 8 floats per thread
    int row = idx >> 7, c8 = idx & 127;
    const float4* in4 = (const float4*)inputs;
    float4 v0 = in4[(size_t)row * 256 + c8 * 2];
    float4 v1 = in4[(size_t)row * 256 + c8 * 2 + 1];
    __half2 h0 = __floats2half2_rn(v0.x, v0.y);
    __half2 h1 = __floats2half2_rn(v0.z, v0.w);
    __half2 h2 = __floats2half2_rn(v1.x, v1.y);
    __half2 h3 = __floats2half2_rn(v1.z, v1.w);
    uint4 u = make_uint4(*(uint32_t*)&h0, *(uint32_t*)&h1,
                         *(uint32_t*)&h2, *(uint32_t*)&h3);
    *(uint4*)&g_hidden[(size_t)row * HID3 + 2048 + c8 * 8] = u;
}

// ---------------- FP16 tensor-core GEMM (f32 acc, ldmatrix, BK=64) -----------
// C[M,N] = A[M,K] @ Bt[N,K]^T. A row-major halves (lda), Bt K-major rows (ldb).
template <typename OutT>
__global__ __launch_bounds__(256, 2)
void h16gemm(const __half* __restrict__ A, const __half* __restrict__ Bt,
             OutT* __restrict__ C, int K, int lda, int ldb, int ldc) {
    extern __shared__ __half smem[];
    __half (*As)[ASTRH] = (__half (*)[ASTRH])smem;                       // [2*BM]
    __half (*Bs)[ASTRH] = (__half (*)[ASTRH])(smem + 2 * BM * ASTRH);    // [2*BN]

    const int tid = threadIdx.x;
    const int bm = blockIdx.y * BM;
    const int bn = blockIdx.x * BN;

    const int lane = tid & 31, wid = tid >> 5;
    const int wm = (wid >> 2) * 64;
    const int wn = (wid & 3) * 32;
    const int g = lane >> 2, t = lane & 3;

    // ldmatrix lane map: lanes 0-15 -> rows 0-15 (k+0), lanes 16-31 -> rows (k+8)
    const int lrow = lane & 15;
    const int khalf = (lane >> 4) * 8;
    const uint32_t aBase = (uint32_t)__cvta_generic_to_shared(&As[wm + lrow][khalf]);
    const uint32_t bBase = (uint32_t)__cvta_generic_to_shared(&Bs[wn + lrow][khalf]);

    float acc[4][4][4];
#pragma unroll
    for (int mt = 0; mt < 4; mt++)
#pragma unroll
        for (int nt = 0; nt < 4; nt++)
#pragma unroll
            for (int i = 0; i < 4; i++) acc[mt][nt][i] = 0.f;

    const int niter = K / BK;

    // 1024 cp16 per operand tile / 256 threads = 4 each; row = j>>3, c8 = j&7
#define LOAD_STAGE(buf, it)                                                   \
    {                                                                         \
        _Pragma("unroll")                                                     \
        for (int tt = 0; tt < 4; tt++) {                                      \
            int j = tid + tt * 256;                                           \
            int row = j >> 3, c8 = j & 7;                                     \
            cp16(&As[(buf) * BM + row][c8 * 8],                               \
                 A + (size_t)(bm + row) * lda + (it) * BK + c8 * 8);          \
        }                                                                     \
        _Pragma("unroll")                                                     \
        for (int tt = 0; tt < 4; tt++) {                                      \
            int j = tid + tt * 256;                                           \
            int row = j >> 3, c8 = j & 7;                                     \
            cp16(&Bs[(buf) * BN + row][c8 * 8],                               \
                 Bt + (size_t)(bn + row) * ldb + (it) * BK + c8 * 8);         \
        }                                                                     \
        asm volatile("cp.async.commit_group;");                               \
    }

    LOAD_STAGE(0, 0)

    for (int i = 0; i < niter; i++) {
        if (i + 1 < niter) {
            LOAD_STAGE((i + 1) & 1, i + 1)
            asm volatile("cp.async.wait_group 1;");
        } else {
            asm volatile("cp.async.wait_group 0;");
        }
        __syncthreads();

        const uint32_t aOff = aBase + (i & 1) * (BM * ASTRH * 2);
        const uint32_t bOff = bBase + (i & 1) * (BN * ASTRH * 2);
#pragma unroll
        for (int ks = 0; ks < 4; ks++) {
            const uint32_t kOff = ks * 32;   // 16 halves = 32 bytes
            uint32_t af[4][4], bf[4][2];
#pragma unroll
            for (int mt = 0; mt < 4; mt++)
                ldsm4(af[mt], aOff + mt * (16 * ASTRH * 2) + kOff);
#pragma unroll
            for (int np = 0; np < 2; np++) {
                uint32_t r[4];
                ldsm4(r, bOff + np * (16 * ASTRH * 2) + kOff);
                bf[np * 2 + 0][0] = r[0];
                bf[np * 2 + 1][0] = r[1];
                bf[np * 2 + 0][1] = r[2];
                bf[np * 2 + 1][1] = r[3];
            }
#pragma unroll
            for (int mt = 0; mt < 4; mt++)
#pragma unroll
                for (int nt = 0; nt < 4; nt++)
                    mma_f16(acc[mt][nt], af[mt], bf[nt]);
        }
        __syncthreads();
    }
#undef LOAD_STAGE

    OutT* Cb = C + (size_t)(bm + wm) * ldc + bn + wn;
#pragma unroll
    for (int mt = 0; mt < 4; mt++) {
#pragma unroll
        for (int nt = 0; nt < 4; nt++) {
            const int r0 = mt * 16 + g;
            const int c0 = nt * 8 + t * 2;
            store2(&Cb[(size_t)r0 * ldc + c0], acc[mt][nt][0], acc[mt][nt][1]);
            store2(&Cb[(size_t)(r0 + 8) * ldc + c0], acc[mt][nt][2], acc[mt][nt][3]);
        }
    }
}

// ---------------- chunked complex scan (g_hidden cols 0..2047, fp16 I/O) -----
__global__ void scan_ends() {
    int gidx = blockIdx.x * blockDim.x + threadIdx.x;
    int h = gidx & 1023, chunk = gidx >> 10;
    float lr = g_lam_re[h], li = g_lam_im[h];
    float sr = 0.f, si = 0.f;
    size_t base = (size_t)chunk * L_CHUNK * HID3 + h;
#pragma unroll 4
    for (int tt = 0; tt < L_CHUNK; tt++) {
        float br = __half2float(g_hidden[base + (size_t)tt * HID3]);
        float bi = __half2float(g_hidden[base + (size_t)tt * HID3 + 1024]);
        float nr = fmaf(lr, sr, fmaf(-li, si, br));
        float ni = fmaf(lr, si, fmaf(li, sr, bi));
        sr = nr; si = ni;
    }
    g_end_re[chunk * HID + h] = sr;
    g_end_im[chunk * HID + h] = si;
}

__global__ void scan_carries() {
    int h = blockIdx.x * blockDim.x + threadIdx.x;
    float lr = g_lamL_re[h], li = g_lamL_im[h];
    float cr = 0.f, ci = 0.f;
    for (int c = 0; c < NCHUNK; c++) {
        g_carry_re[c * HID + h] = cr;
        g_carry_im[c * HID + h] = ci;
        float er = g_end_re[c * HID + h], ei = g_end_im[c * HID + h];
        float nr = fmaf(lr, cr, fmaf(-li, ci, er));
        float ni = fmaf(lr, ci, fmaf(li, cr, ei));
        cr = nr; ci = ni;
    }
}

__global__ void scan_apply() {
    int gidx = blockIdx.x * blockDim.x + threadIdx.x;
    int h = gidx & 1023, chunk = gidx >> 10;
    float lr = g_lam_re[h], li = g_lam_im[h];
    float sr = g_carry_re[chunk * HID + h];
    float si = g_carry_im[chunk * HID + h];
    size_t base = (size_t)chunk * L_CHUNK * HID3 + h;
#pragma unroll 4
    for (int tt = 0; tt < L_CHUNK; tt++) {
        float br = __half2float(g_hidden[base + (size_t)tt * HID3]);
        float bi = __half2float(g_hidden[base + (size_t)tt * HID3 + 1024]);
        float nr = fmaf(lr, sr, fmaf(-li, si, br));
        float ni = fmaf(lr, si, fmaf(li, sr, bi));
        sr = nr; si = ni;
        g_hidden[base + (size_t)tt * HID3]        = __float2half_rn(sr);
        g_hidden[base + (size_t)tt * HID3 + 1024] = __float2half_rn(si);
    }
}

// ---------------- launch -----------------------------------------------------
extern "C" void kernel_launch(void* const* d_in, const int* in_sizes, int n_in,
                              void* d_out, int out_size) {
    const float* inputs    = (const float*)d_in[0];
    const float* nu_log    = (const float*)d_in[1];
    const float* theta_log = (const float*)d_in[2];
    const float* gamma_log = (const float*)d_in[3];
    const float* B_re      = (const float*)d_in[4];
    const float* B_im      = (const float*)d_in[5];
    const float* C_re      = (const float*)d_in[6];
    const float* C_im      = (const float*)d_in[7];
    const float* Dmat      = (const float*)d_in[8];
    float* out = (float*)d_out;

    __half *hidden, *bcat, *w2;
    cudaGetSymbolAddress((void**)&hidden, g_hidden);
    cudaGetSymbolAddress((void**)&bcat, g_bcat);
    cudaGetSymbolAddress((void**)&w2, g_w2);

    cudaFuncSetAttribute(h16gemm<__half>,
                         cudaFuncAttributeMaxDynamicSharedMemorySize, SMEM_BYTES);
    cudaFuncSetAttribute(h16gemm<float>,
                         cudaFuncAttributeMaxDynamicSharedMemorySize, SMEM_BYTES);

    prep_lambda<<<1, HID>>>(nu_log, theta_log);
    prep_bcat<<<dim3(32, 32), dim3(32, 8)>>>(B_re, B_im, gamma_log);
    prep_w2_c<<<(HID * 2048) / 256, 256>>>(C_re, C_im);
    prep_w2_d<<<dim3(32, 32), dim3(32, 8)>>>(Dmat);
    copy_inputs<<<(T_LEN * HID / 8) / 256, 256>>>(inputs);

    // GEMM1: hidden[:, :2048] = u16 @ bcat^T   [16384,1024]x[2048,1024]^T
    h16gemm<__half><<<dim3(2048 / BN, T_LEN / BM), 256, SMEM_BYTES>>>(
        hidden + 2048, bcat, hidden, HID, HID3, HID, HID3);

    // complex diagonal scan, in-place
    scan_ends<<<(NCHUNK * HID) / 256, 256>>>();
    scan_carries<<<HID / 256, 256>>>();
    scan_apply<<<(NCHUNK * HID) / 256, 256>>>();

    // GEMM2: out = [h_re|h_im|inputs] @ w2^T   [16384,3072]x[1024,3072]^T
    h16gemm<float><<<dim3(HID / BN, T_LEN / BM), 256, SMEM_BYTES>>>(
        hidden, w2, out, HID3, HID3, HID3, HID);
}